// round 13
// baseline (speedup 1.0000x reference)
#include <cuda_runtime.h>
#include <math.h>

#define BATCH 32
#define H 512
#define W 512
#define HW (H*W)
#define NTOT (BATCH*HW)
#define KK_INV (1.0f/961.0f)

#define ROWS_PW 16
#define COLS_PW 128
#define NSWATH (W / COLS_PW)                    // 4
#define NSTRIP (H / ROWS_PW)                    // 32
#define WARPS_PER_IMG (NSWATH * NSTRIP)         // 128
#define NWARPG (BATCH * WARPS_PER_IMG)          // 4096
#define NTHR 256
#define NBLK (NWARPG / 8)                       // 512

__device__ float g_part[NWARPG][4];             // {bce, wsum, inter, union}
__device__ unsigned g_done = 0;

// float4 load with row/col validity -> zeros (implements zero padding)
__device__ __forceinline__ float4 ld4z(const float* __restrict__ p, int row,
                                       int col4, bool colvalid) {
    if (!colvalid || row < 0 || row >= H) return make_float4(0.f, 0.f, 0.f, 0.f);
    return __ldg(((const float4*)p) + (size_t)row * (W/4) + col4);
}

__device__ __forceinline__ void lane_math(float xv, float tv, float pool,
                                          float& bce, float& ws, float& it, float& un) {
    const float w   = fmaf(5.0f, fabsf(pool - tv), 1.0f);
    const float E   = __expf(-fabsf(xv));
    const float u   = 1.0f + E;
    const float sp  = fmaxf(xv, 0.0f) + __logf(u);
    const float inv = __fdividef(1.0f, u);
    const float p   = (xv >= 0.0f) ? inv : E * inv;
    bce += sp - xv * tv;
    ws  += w;
    it  += p * tv * w;
    un  += (p + tv) * w;
}

// ---------------------------------------------------------------------------
// Barrier-free fused kernel. Each warp independently owns a 128-col x 16-row
// tile: vertical 31-row sliding sums in registers (main quad per lane + one
// halo quad on lanes 0-7), horizontal 31-sum via warp scan per output row.
// ---------------------------------------------------------------------------
__global__ __launch_bounds__(NTHR, 4)
void fused_kernel(const float* __restrict__ pred,
                  const float* __restrict__ targ,
                  float* __restrict__ out) {
    const unsigned FULL = 0xffffffffu;
    const int tid  = threadIdx.x;
    const int lane = tid & 31;
    const int wg   = blockIdx.x * (NTHR / 32) + (tid >> 5);   // global warp id

    const int b     = wg >> 7;                 // image
    const int rem   = wg & 127;
    const int strip = rem >> 2;
    const int sw    = rem & 3;
    const int r0    = strip * ROWS_PW;
    const int X0q   = sw * (COLS_PW / 4);      // first main float4 index

    const float* __restrict__ tb = targ + (size_t)b * HW;
    const float* __restrict__ pb = pred + (size_t)b * HW;

    const int qm = X0q + lane;                 // this lane's main quad
    int qh; bool hv;
    if (lane < 4)      { qh = X0q - 4 + lane;        hv = (qh >= 0); }
    else if (lane < 8) { qh = X0q + 32 + (lane - 4); hv = (qh < W/4); }
    else               { qh = 0;                      hv = false; }

    // Build initial vertical window: rows r0-15 .. r0+15
    float4 vm = make_float4(0.f, 0.f, 0.f, 0.f);
    float4 vh = make_float4(0.f, 0.f, 0.f, 0.f);
    for (int i = -15; i <= 15; ++i) {
        float4 a = ld4z(tb, r0 + i, qm, true);
        vm.x += a.x; vm.y += a.y; vm.z += a.z; vm.w += a.w;
        float4 h = ld4z(tb, r0 + i, qh, hv);
        vh.x += h.x; vh.y += h.y; vh.z += h.z; vh.w += h.w;
    }

    float bce_a = 0.f, wsum_a = 0.f, inter_a = 0.f, uni_a = 0.f;

    #pragma unroll 1
    for (int r = r0; r < r0 + ROWS_PW; ++r) {
        // loads for this row (independent of scan chain)
        const float4 tv = __ldg(((const float4*)tb) + (size_t)r * (W/4) + qm);
        const float4 xv = __ldg(((const float4*)pb) + (size_t)r * (W/4) + qm);
        const float4 am = ld4z(tb, r + 16, qm, true);
        const float4 sm = ld4z(tb, r - 15, qm, true);
        const float4 ah = ld4z(tb, r + 16, qh, hv);
        const float4 sh = ld4z(tb, r - 15, qh, hv);

        // ---- horizontal 31-sum of the vertical sums ----
        // intra-quad inclusive prefixes
        const float m0 = vm.x, m1 = m0 + vm.y, m2 = m1 + vm.z, m3 = m2 + vm.w;
        const float h0 = vh.x, h1 = h0 + vh.y, h2 = h1 + vh.z, h3 = h2 + vh.w;

        // main: warp inclusive scan of quad totals
        float s = m3;
        #pragma unroll
        for (int off = 1; off < 32; off <<= 1) {
            float n = __shfl_up_sync(FULL, s, off);
            if (lane >= off) s += n;
        }
        const float basem = s - m3;                 // exclusive
        const float Tmain = __shfl_sync(FULL, s, 31);

        // halo: segmented (4-wide) inclusive scan of halo quad totals
        float hs = h3;
        float t1 = __shfl_up_sync(FULL, hs, 1); if ((lane & 3) >= 1) hs += t1;
        float t2 = __shfl_up_sync(FULL, hs, 2); if ((lane & 3) >= 2) hs += t2;
        const float hbase = hs - h3;
        const float Lsum  = __shfl_sync(FULL, hs, 3);   // left-halo total

        // inclusive global prefixes G (origin at col X0-16; zero-pad automatic)
        const float4 Gm = make_float4(Lsum + basem + m0, Lsum + basem + m1,
                                      Lsum + basem + m2, Lsum + basem + m3);
        const float4 Gl = make_float4(hbase + h0, hbase + h1, hbase + h2, hbase + h3);
        const float grb = Lsum + Tmain;
        const float4 Gr = make_float4(grb + hbase + h0, grb + hbase + h1,
                                      grb + hbase + h2, grb + hbase + h3);

        // A_j = G[x+15], B_j = G[x-16] for the 4 cols of this lane's quad
        const int lp3 = (lane + 3) & 31, lp4 = (lane + 4) & 31, lm4 = (lane - 4) & 31;
        const int rl3 = (lane - 25) & 31, rl4 = (lane - 24) & 31;

        float A0m = __shfl_sync(FULL, Gm.w, lp3), A0r = __shfl_sync(FULL, Gr.w, rl3);
        float A1m = __shfl_sync(FULL, Gm.x, lp4), A1r = __shfl_sync(FULL, Gr.x, rl4);
        float A2m = __shfl_sync(FULL, Gm.y, lp4), A2r = __shfl_sync(FULL, Gr.y, rl4);
        float A3m = __shfl_sync(FULL, Gm.z, lp4), A3r = __shfl_sync(FULL, Gr.z, rl4);
        const float A0 = (lane <= 28) ? A0m : A0r;
        const float A1 = (lane <= 27) ? A1m : A1r;
        const float A2 = (lane <= 27) ? A2m : A2r;
        const float A3 = (lane <= 27) ? A3m : A3r;

        float B0m = __shfl_sync(FULL, Gm.x, lm4);
        float B1m = __shfl_sync(FULL, Gm.y, lm4);
        float B2m = __shfl_sync(FULL, Gm.z, lm4);
        float B3m = __shfl_sync(FULL, Gm.w, lm4);
        const float B0 = (lane >= 4) ? B0m : Gl.x;
        const float B1 = (lane >= 4) ? B1m : Gl.y;
        const float B2 = (lane >= 4) ? B2m : Gl.z;
        const float B3 = (lane >= 4) ? B3m : Gl.w;

        lane_math(xv.x, tv.x, (A0 - B0) * KK_INV, bce_a, wsum_a, inter_a, uni_a);
        lane_math(xv.y, tv.y, (A1 - B1) * KK_INV, bce_a, wsum_a, inter_a, uni_a);
        lane_math(xv.z, tv.z, (A2 - B2) * KK_INV, bce_a, wsum_a, inter_a, uni_a);
        lane_math(xv.w, tv.w, (A3 - B3) * KK_INV, bce_a, wsum_a, inter_a, uni_a);

        // vertical slide
        vm.x += am.x - sm.x; vm.y += am.y - sm.y;
        vm.z += am.z - sm.z; vm.w += am.w - sm.w;
        vh.x += ah.x - sh.x; vh.y += ah.y - sh.y;
        vh.z += ah.z - sh.z; vh.w += ah.w - sh.w;
    }

    // Deterministic warp butterfly reduction
    #pragma unroll
    for (int off = 16; off > 0; off >>= 1) {
        bce_a   += __shfl_xor_sync(FULL, bce_a,   off);
        wsum_a  += __shfl_xor_sync(FULL, wsum_a,  off);
        inter_a += __shfl_xor_sync(FULL, inter_a, off);
        uni_a   += __shfl_xor_sync(FULL, uni_a,   off);
    }
    if (lane == 0) {
        g_part[wg][0] = bce_a;
        g_part[wg][1] = wsum_a;
        g_part[wg][2] = inter_a;
        g_part[wg][3] = uni_a;
    }

    // ---- last-block finalize ----
    __shared__ unsigned last_flag;
    __shared__ float red[NTHR];
    __shared__ float res[BATCH];
    __syncthreads();
    if (tid == 0) {
        __threadfence();
        last_flag = (atomicAdd(&g_done, 1u) == (unsigned)(NBLK - 1));
    }
    __syncthreads();
    if (!last_flag) return;

    __threadfence();
    if (tid == 0) g_done = 0;     // reset for next graph replay

    float acc = 0.0f;
    #pragma unroll
    for (int j = 0; j < NWARPG / NTHR; ++j)
        acc += g_part[tid * (NWARPG / NTHR) + j][0];
    red[tid] = acc;
    __syncthreads();
    #pragma unroll
    for (int off = NTHR / 2; off > 0; off >>= 1) {
        if (tid < off) red[tid] += red[tid + off];
        __syncthreads();
    }
    const float bce = red[0] * (1.0f / (float)NTOT);

    if (tid < BATCH) {
        float ws = 0.0f, it = 0.0f, un = 0.0f;
        for (int j = 0; j < WARPS_PER_IMG; ++j) {
            const int e = tid * WARPS_PER_IMG + j;
            ws += g_part[e][1];
            it += g_part[e][2];
            un += g_part[e][3];
        }
        const float w_bce = (ws * bce + 1e-8f) / (ws + 1e-8f);
        const float w_iou = 1.0f - (it + 1.0f + 1e-8f) / (un - it + 1.0f + 1e-8f);
        res[tid] = w_bce + w_iou;
    }
    __syncthreads();
    if (tid == 0) {
        float a = 0.0f;
        #pragma unroll
        for (int i = 0; i < BATCH; ++i) a += res[i];
        out[0] = a * (1.0f / (float)BATCH);
    }
}

// ---------------------------------------------------------------------------
extern "C" void kernel_launch(void* const* d_in, const int* in_sizes, int n_in,
                              void* d_out, int out_size) {
    const float* y_pred   = (const float*)d_in[0];
    const float* y_target = (const float*)d_in[1];
    float* out = (float*)d_out;

    fused_kernel<<<NBLK, NTHR>>>(y_pred, y_target, out);
}